// round 6
// baseline (speedup 1.0000x reference)
#include <cuda_runtime.h>
#include <cooperative_groups.h>

namespace cg = cooperative_groups;

// ============================================================================
// CapLayerLP PDIP QP (n=1024, m=2051): diag + rank-2 KKT -> Woodbury (2x2).
// Cluster of 8 CTAs x 128 threads (1 coord/thread), DSMEM mailbox all-reduce.
//
// Round-6: 5 reduce rounds/iter -> 3 by exploiting that the predictor and
// corrector RHS are AFFINE in the post-reduce scalars:
//   g   = gbase - (T0 + fi*TAB)*invD                      (predictor)
//   g_c = gcb  - (T0c + fi*TABc)*invD - smu*cw            (corrector)
// so Sum(g), Sum(f g) are recovered analytically from Sum(gbase), Sum(f gbase),
// SiD, SfD (and Scw, Sfcw for the corrector). Fuses rounds A+B and C+D.
// smu uses pre-hoisted 1/mu (no divide on the post-round-2 critical path).
// ============================================================================

#define CL    8
#define T     128
#define NWARP 4
#define NV    1024
#define IMCON (1.0/2051.0)
#define EPSR  1e-4
#define CCAP  10.0
#define ITERS 20

__device__ __forceinline__ double wsum(double v) {
#pragma unroll
    for (int o = 16; o > 0; o >>= 1) v += __shfl_down_sync(0xffffffffu, v, o);
    return v;
}
__device__ __forceinline__ double wmaxr(double v) {
#pragma unroll
    for (int o = 16; o > 0; o >>= 1) v = fmax(v, __shfl_down_sync(0xffffffffu, v, o));
    return v;
}
__device__ __forceinline__ void wpairmax(double& n, double& d) {
#pragma unroll
    for (int o = 16; o > 0; o >>= 1) {
        double n2 = __shfl_xor_sync(0xffffffffu, n, o);
        double d2 = __shfl_xor_sync(0xffffffffu, d, o);
        if (n2 * d > n * d2) { n = n2; d = d2; }
    }
}

__global__ void __launch_bounds__(T, 1) __cluster_dims__(CL, 1, 1)
pdip_kernel(const float* __restrict__ xin, const int* __restrict__ male,
            float* __restrict__ out)
{
    cg::cluster_group cluster = cg::this_cluster();
    const unsigned rank = cluster.block_rank();
    const int i    = threadIdx.x;
    const int lane = i & 31;
    const int wid  = i >> 5;

    __shared__ double lpart[NWARP][7];
    __shared__ double mbox[2][CL][7];

    const int c = (int)rank * T + i;
    const double pi = -(double)xin[c];
    const double fi = (double)male[c];
    double xi = 0.0, s1 = 1.0, z1 = 1.0, s2 = 1.0, z2 = 1.0;

    // ---- init: n_male all-reduce ----
    {
        double v = wsum(fi);
        if (lane == 0) lpart[wid][0] = v;
        __syncthreads();
        if (wid == 0 && lane < CL) {
            double t = lpart[0][0] + lpart[1][0] + lpart[2][0] + lpart[3][0];
            *cluster.map_shared_rank(&mbox[0][rank][0], lane) = t;
        }
        cluster.sync();
    }
    double nm = 0.0;
#pragma unroll
    for (int r = 0; r < CL; ++r) nm += mbox[0][r][0];
    const double hA = CCAP * nm / (double)NV + 1.0;
    const double hB = -(CCAP * nm / (double)NV);

    double s0 = 1.0, sA = 1.0, sB = 1.0;
    double z0 = 1.0, zA = 1.0, zB = 1.0;
    int pb = 1;

    for (int it = 0; it < ITERS; ++it) {
        // scalar reciprocals (prev-state only; overlap with round-1 vector work)
        const double inv_sss = 1.0 / (s0 * sA * sB);
        const double is0 = sA * sB * inv_sss;
        const double isA = s0 * sB * inv_sss;
        const double isB = s0 * sA * inv_sss;
        const double w0 = z0 * is0, wA = zA * isA, wB = zB * isB;
        const double M11p = s0 / z0;
        const double M22p = 1.0 / (wA + wB);

        // ================= Round 1 (fused A+B) =================
        const double ss    = s1 * s2;
        const double invss = 1.0 / ss;
        const double invs1 = s2 * invss;
        const double invs2 = s1 * invss;
        const double den   = fma((double)EPSR, ss, fma(z1, s2, z2 * s1));
        const double invD  = ss / den;
        const double rp1 = s1 - xi;
        const double rp2 = xi + s2 - 1.0;
        const double w1  = z1 * invs1;
        const double w2  = z2 * invs2;
        const double rx  = EPSR*xi + pi + (z0 - z1 + z2 + fi*(zA - zB));
        const double t1v = w1*rp1 - z1;
        const double t2v = w2*rp2 - z2;
        const double gbase = -(rx - t1v + t2v) * invD;
        {
            double v0 = wsum(xi);
            double v1 = wsum(fi * xi);
            double v2 = wsum(s1 * z1 + s2 * z2);
            double v3 = wsum(invD);
            double v4 = wsum(fi * invD);
            double v5 = wsum(gbase);
            double v6 = wsum(fi * gbase);
            if (lane == 0) {
                lpart[wid][0]=v0; lpart[wid][1]=v1; lpart[wid][2]=v2;
                lpart[wid][3]=v3; lpart[wid][4]=v4; lpart[wid][5]=v5;
                lpart[wid][6]=v6;
            }
        }
        __syncthreads();
        if (wid == 0 && lane < CL) {
            double* dst = cluster.map_shared_rank(&mbox[pb][rank][0], lane);
#pragma unroll
            for (int s = 0; s < 7; ++s)
                dst[s] = lpart[0][s] + lpart[1][s] + lpart[2][s] + lpart[3][s];
        }
        cluster.sync();
        double sumx=0, fx=0, szv=0, SiD=0, SfD=0, Sg0=0, Sfg0=0;
#pragma unroll
        for (int r = 0; r < CL; ++r) {
            sumx += mbox[pb][r][0];  fx  += mbox[pb][r][1];
            szv  += mbox[pb][r][2];  SiD += mbox[pb][r][3];
            SfD  += mbox[pb][r][4];  Sg0 += mbox[pb][r][5];
            Sfg0 += mbox[pb][r][6];
        }
        pb ^= 1;

        // post-round-1 scalar algebra (replicated everywhere)
        const double rp0 = sumx + s0 - CCAP;
        const double rpA =  fx + sA - hA;
        const double rpB = -fx + sB - hB;
        const double SZTOT = szv + s0*z0 + sA*zA + sB*zB;
        const double mu  = SZTOT * IMCON;
        const double imu = 1.0 / mu;
        const double T0 = w0*rp0 - z0;
        const double TA = wA*rpA - zA;
        const double TB = wB*rpB - zB;
        const double TAB = TA - TB;
        const double M11 = M11p + SiD;
        const double M22 = M22p + SfD;
        const double M12 = SfD;
        const double detinv = 1.0 / (M11*M22 - M12*M12);
        const double u1 = Sg0  - T0*SiD - TAB*SfD;          // analytic Sum(g)
        const double uf = Sfg0 - (T0 + TAB)*SfD;            // analytic Sum(f g)
        const double Y1 = (M22*u1 - M12*uf) * detinv;
        const double Y2 = (M11*uf - M12*u1) * detinv;
        const double sdx = u1 - Y1*SiD - Y2*SfD;
        const double fdx = uf - (Y1 + Y2)*SfD;
        const double ds0 = -rp0 - sdx;
        const double dsA = -rpA - fdx;
        const double dsB = -rpB + fdx;
        const double dz0 = -z0 - w0*ds0;
        const double dzA = -zA - wA*dsA;
        const double dzB = -zB - wB*dsB;
        double sc_q = fmax(fmax(-ds0,0.0)*is0, fmax(fmax(-dsA,0.0)*isA, fmax(-dsB,0.0)*isB));
        sc_q = fmax(sc_q, fmax(1.0 + ds0*is0, 0.0));
        sc_q = fmax(sc_q, fmax(1.0 + dsA*isA, 0.0));
        sc_q = fmax(sc_q, fmax(1.0 + dsB*isB, 0.0));

        // ================= Round 2 (fused C+D) =================
        double prod1, prod2, gcb, cw;
        {
            double g  = gbase - (T0 + fi*TAB) * invD;        // predictor g
            double dx = g - (Y1 + fi*Y2) * invD;             // affine dir
            double ds1 = dx - rp1,  ds2 = -rp2 - dx;
            double dz1 = -z1 - w1*ds1;
            double dz2 = -z2 - w2*ds2;
            double r1 = ds1 * invs1, r2 = ds2 * invs2;
            double mq = fmax(sc_q, fmax(fmax(-r1, 0.0), fmax(-r2, 0.0)));
            mq = fmax(mq, fmax(fmax(1.0 + r1, 0.0), fmax(1.0 + r2, 0.0)));
            prod1 = ds1 * dz1;
            prod2 = ds2 * dz2;
            // corrector base (smu/T0c/TABc factored out analytically)
            double t1b = (z1*rp1 - s1*z1 - prod1) * invs1;
            double t2b = (z2*rp2 - s2*z2 - prod2) * invs2;
            gcb = -(rx + t2b - t1b) * invD;
            cw  = (invs2 - invs1) * invD;
            double v0 = wsum(prod1 + prod2);
            double v1 = wmaxr(mq);
            double v2 = wsum(gcb);
            double v3 = wsum(fi * gcb);
            double v4 = wsum(cw);
            double v5 = wsum(fi * cw);
            if (lane == 0) {
                lpart[wid][0]=v0; lpart[wid][1]=v1; lpart[wid][2]=v2;
                lpart[wid][3]=v3; lpart[wid][4]=v4; lpart[wid][5]=v5;
            }
        }
        __syncthreads();
        if (wid == 0 && lane < CL) {
            double* dst = cluster.map_shared_rank(&mbox[pb][rank][0], lane);
            dst[0] = lpart[0][0] + lpart[1][0] + lpart[2][0] + lpart[3][0];
            dst[1] = fmax(fmax(lpart[0][1], lpart[1][1]), fmax(lpart[2][1], lpart[3][1]));
            dst[2] = lpart[0][2] + lpart[1][2] + lpart[2][2] + lpart[3][2];
            dst[3] = lpart[0][3] + lpart[1][3] + lpart[2][3] + lpart[3][3];
            dst[4] = lpart[0][4] + lpart[1][4] + lpart[2][4] + lpart[3][4];
            dst[5] = lpart[0][5] + lpart[1][5] + lpart[2][5] + lpart[3][5];
        }
        cluster.sync();
        double S2v=0, qmax=0, Sgc=0, Sfgc=0, Scw=0, Sfcw=0;
#pragma unroll
        for (int r = 0; r < CL; ++r) {
            S2v  += mbox[pb][r][0];
            qmax  = fmax(qmax, mbox[pb][r][1]);
            Sgc  += mbox[pb][r][2];
            Sfgc += mbox[pb][r][3];
            Scw  += mbox[pb][r][4];
            Sfcw += mbox[pb][r][5];
        }
        pb ^= 1;

        // post-round-2 scalar algebra
        const double aaff = (qmax > 0.0) ? fmin(1.0, 1.0 / qmax) : 1.0;
        const double S2t  = S2v + ds0*dz0 + dsA*dzA + dsB*dzB;
        const double muaff = fma(aaff*aaff, S2t, SZTOT*(1.0 - aaff)) * IMCON;
        const double smu = muaff * muaff * muaff * (imu * imu);   // (muaff/mu)^3 * mu
        const double rsz0 = s0*z0 + ds0*dz0 - smu;
        const double rszA = sA*zA + dsA*dzA - smu;
        const double rszB = sB*zB + dsB*dzB - smu;
        const double T0c = (z0*rp0 - rsz0) * is0;
        const double TAc = (zA*rpA - rszA) * isA;
        const double TBc = (zB*rpB - rszB) * isB;
        const double TABc = TAc - TBc;
        const double u1c = Sgc  - T0c*SiD - TABc*SfD - smu*Scw;
        const double ufc = Sfgc - (T0c + TABc)*SfD   - smu*Sfcw;
        const double Y1c = (M22*u1c - M12*ufc) * detinv;
        const double Y2c = (M11*ufc - M12*u1c) * detinv;
        const double sdxc = u1c - Y1c*SiD - Y2c*SfD;
        const double fdxc = ufc - (Y1c + Y2c)*SfD;
        const double ds0c = -rp0 - sdxc;
        const double dsAc = -rpA - fdxc;
        const double dsBc = -rpB + fdxc;
        const double dz0c = -(rsz0 + z0*ds0c) * is0;
        const double dzAc = -(rszA + zA*dsAc) * isA;
        const double dzBc = -(rszB + zB*dsBc) * isB;
        double sc_qs = fmax(fmax(-ds0c,0.0)*is0,
                       fmax(fmax(-dsAc,0.0)*isA, fmax(-dsBc,0.0)*isB));
        double scn = fmax(-dz0c, 0.0), scd = z0;
        { double n2 = fmax(-dzAc,0.0), d2 = zA; if (n2*scd > scn*d2) { scn=n2; scd=d2; } }
        { double n2 = fmax(-dzBc,0.0), d2 = zB; if (n2*scd > scn*d2) { scn=n2; scd=d2; } }

        // ================= Round 3 (corrector dir + step) =================
        double dxc, ds1c, ds2c, dz1c, dz2c;
        {
            double gc = gcb - (T0c + fi*TABc)*invD - smu*cw;   // corrector g
            dxc  = gc - (Y1c + fi*Y2c) * invD;
            ds1c = dxc - rp1;
            ds2c = -rp2 - dxc;
            double rsz1 = s1*z1 + prod1 - smu;
            double rsz2 = s2*z2 + prod2 - smu;
            dz1c = -(rsz1 + z1*ds1c) * invs1;
            dz2c = -(rsz2 + z2*ds2c) * invs2;
            double mqs = fmax(sc_qs, fmax(fmax(-ds1c,0.0)*invs1, fmax(-ds2c,0.0)*invs2));
            double n1 = fmax(-dz1c, 0.0), d1v = z1;
            double n2 = fmax(-dz2c, 0.0), d2v = z2;
            if (n2*d1v > n1*d2v) { n1 = n2; d1v = d2v; }
            double pn = scn, pd = scd;
            if (n1*pd > pn*d1v)  { pn = n1; pd = d1v; }
            mqs = wmaxr(mqs);
            wpairmax(pn, pd);
            if (lane == 0) { lpart[wid][0] = mqs; lpart[wid][1] = pn; lpart[wid][2] = pd; }
        }
        __syncthreads();
        if (wid == 0 && lane < CL) {
            double mq = fmax(fmax(lpart[0][0], lpart[1][0]), fmax(lpart[2][0], lpart[3][0]));
            double pn = lpart[0][1], pd = lpart[0][2];
#pragma unroll
            for (int w = 1; w < NWARP; ++w) {
                double n2 = lpart[w][1], d2 = lpart[w][2];
                if (n2*pd > pn*d2) { pn = n2; pd = d2; }
            }
            double* dst = cluster.map_shared_rank(&mbox[pb][rank][0], lane);
            dst[0] = mq; dst[1] = pn; dst[2] = pd;
        }
        cluster.sync();
        double mqs = 0, pn = mbox[pb][0][1], pd = mbox[pb][0][2];
#pragma unroll
        for (int r = 0; r < CL; ++r) mqs = fmax(mqs, mbox[pb][r][0]);
#pragma unroll
        for (int r = 1; r < CL; ++r) {
            double n2 = mbox[pb][r][1], d2 = mbox[pb][r][2];
            if (n2*pd > pn*d2) { pn = n2; pd = d2; }
        }
        pb ^= 1;

        if (mqs * pd > pn) { pn = mqs; pd = 1.0; }
        const double st = (pn > 0.0) ? fmin(1.0, pd / pn) : 1.0;
        const double alpha = 0.99 * st;

        s0 += alpha*ds0c;  sA += alpha*dsAc;  sB += alpha*dsBc;
        z0 += alpha*dz0c;  zA += alpha*dzAc;  zB += alpha*dzBc;
        xi += alpha*dxc;
        s1 += alpha*ds1c;  z1 += alpha*dz1c;
        s2 += alpha*ds2c;  z2 += alpha*dz2c;
    }

    out[c] = (float)xi;
}

extern "C" void kernel_launch(void* const* d_in, const int* in_sizes, int n_in,
                              void* d_out, int out_size)
{
    const float* x    = (const float*)d_in[0];
    const int*   male = (const int*)d_in[1];
    float*       out  = (float*)d_out;
    pdip_kernel<<<CL, T>>>(x, male, out);
}

// round 7
// speedup vs baseline: 1.1268x; 1.1268x over previous
#include <cuda_runtime.h>
#include <cstdint>

// ============================================================================
// CapLayerLP PDIP QP (n=1024, m=2051): diag + rank-2 KKT -> Woodbury (2x2).
// Cluster of 8 CTAs x 128 threads (1 coord/thread).
//
// Round-7 (vs Round-5 winner): replace cluster.sync-based DSMEM all-reduce
// with st.async + mbarrier push all-reduce (sync ~490cyc -> try_wait ~90cyc),
// tree-structured rank/warp combines (8 serial DFADDs -> 3-level tree),
// hoisted 1/mu. 5-round structure of R5 kept (empirically better than the
// fused 3-round R6).
// ============================================================================

#define CL    8
#define T     128
#define NWARP 4
#define NV    1024
#define IMCON (1.0/2051.0)
#define EPSR  1e-4
#define CCAP  10.0
#define ITERS 20

__device__ __forceinline__ double wsum(double v) {
#pragma unroll
    for (int o = 16; o > 0; o >>= 1) v += __shfl_down_sync(0xffffffffu, v, o);
    return v;
}
__device__ __forceinline__ double wmaxr(double v) {
#pragma unroll
    for (int o = 16; o > 0; o >>= 1) v = fmax(v, __shfl_down_sync(0xffffffffu, v, o));
    return v;
}
__device__ __forceinline__ void wpairmax(double& n, double& d) {
#pragma unroll
    for (int o = 16; o > 0; o >>= 1) {
        double n2 = __shfl_xor_sync(0xffffffffu, n, o);
        double d2 = __shfl_xor_sync(0xffffffffu, d, o);
        if (n2 * d > n * d2) { n = n2; d = d2; }
    }
}

// ---- cluster / mbarrier helpers ----
__device__ __forceinline__ uint32_t s2u(const void* p) {
    uint32_t a;
    asm("{ .reg .u64 t; cvta.to.shared.u64 t, %1; cvt.u32.u64 %0, t; }" : "=r"(a) : "l"(p));
    return a;
}
__device__ __forceinline__ uint32_t cta_rank() {
    uint32_t r; asm("mov.u32 %0, %%cluster_ctarank;" : "=r"(r)); return r;
}
__device__ __forceinline__ uint32_t mapa_u32(uint32_t a, uint32_t r) {
    uint32_t ra;
    asm("mapa.shared::cluster.u32 %0, %1, %2;" : "=r"(ra) : "r"(a), "r"(r));
    return ra;
}
__device__ __forceinline__ void mb_init(uint32_t a, uint32_t cnt) {
    asm volatile("mbarrier.init.shared.b64 [%0], %1;" :: "r"(a), "r"(cnt) : "memory");
}
__device__ __forceinline__ void mb_expect(uint32_t a, uint32_t bytes) {
    asm volatile("mbarrier.arrive.expect_tx.shared.b64 _, [%0], %1;"
                 :: "r"(a), "r"(bytes) : "memory");
}
__device__ __forceinline__ void mb_wait(uint32_t a, uint32_t ph) {
    asm volatile(
        "{\n\t.reg .pred P;\n\t"
        "WL_%=:\n\t"
        "mbarrier.try_wait.parity.acquire.cluster.shared::cta.b64 P, [%0], %1, 0x989680;\n\t"
        "@P bra.uni WD_%=;\n\t"
        "bra.uni WL_%=;\n\t"
        "WD_%=:\n\t}"
        :: "r"(a), "r"(ph) : "memory");
}
__device__ __forceinline__ void st_async_d(uint32_t ra, double v, uint32_t rb) {
    asm volatile("st.async.shared::cluster.mbarrier::complete_tx::bytes.u64 [%0], %1, [%2];"
                 :: "r"(ra), "l"(__double_as_longlong(v)), "r"(rb) : "memory");
}

#define TREE4(L, s) (((L)[0][s] + (L)[1][s]) + ((L)[2][s] + (L)[3][s]))
#define TREE8(Mb, s) ((((Mb)[0][s]+(Mb)[1][s])+((Mb)[2][s]+(Mb)[3][s])) + \
                      (((Mb)[4][s]+(Mb)[5][s])+((Mb)[6][s]+(Mb)[7][s])))
#define TREE8MAX(Mb, s) fmax(fmax(fmax((Mb)[0][s],(Mb)[1][s]),fmax((Mb)[2][s],(Mb)[3][s])), \
                             fmax(fmax((Mb)[4][s],(Mb)[5][s]),fmax((Mb)[6][s],(Mb)[7][s])))

__global__ void __launch_bounds__(T, 1) __cluster_dims__(CL, 1, 1)
pdip_kernel(const float* __restrict__ xin, const int* __restrict__ male,
            float* __restrict__ out)
{
    const uint32_t rank = cta_rank();
    const int i    = threadIdx.x;
    const int lane = i & 31;
    const int wid  = i >> 5;

    __shared__ double lpart[NWARP][5];
    __shared__ double mA[CL][5], mB[CL][2], mCx[CL][2], mD[CL][2], mE[CL][3], mI[CL][1];
    __shared__ __align__(8) unsigned long long mbar[6];

    const uint32_t barA = s2u(&mbar[0]);
    const uint32_t barB = s2u(&mbar[1]);
    const uint32_t barC = s2u(&mbar[2]);
    const uint32_t barD = s2u(&mbar[3]);
    const uint32_t barE = s2u(&mbar[4]);
    const uint32_t barI = s2u(&mbar[5]);

    if (i == 0) {
        mb_init(barA, 1); mb_init(barB, 1); mb_init(barC, 1);
        mb_init(barD, 1); mb_init(barE, 1); mb_init(barI, 1);
        mb_expect(barI, CL * 8);
        asm volatile("fence.mbarrier_init.release.cluster;" ::: "memory");
    }
    __syncthreads();
    asm volatile("barrier.cluster.arrive.aligned;" ::: "memory");
    asm volatile("barrier.cluster.wait.aligned;" ::: "memory");

    const int c = (int)rank * T + i;
    const double pi = -(double)xin[c];
    const double fi = (double)male[c];
    double xi = 0.0, s1 = 1.0, z1 = 1.0, s2 = 1.0, z2 = 1.0;

    // ---- init all-reduce: n_male ----
    {
        double v = wsum(fi);
        if (lane == 0) lpart[wid][0] = v;
        __syncthreads();
        if (wid == 0 && lane < CL) {
            double p = TREE4(lpart, 0);
            uint32_t rb = mapa_u32(barI, lane);
            uint32_t ra = mapa_u32(s2u(&mI[rank][0]), lane);
            st_async_d(ra, p, rb);
        }
        mb_wait(barI, 0);
    }
    const double nm = TREE8(mI, 0);
    const double hA = CCAP * nm / (double)NV + 1.0;
    const double hB = -(CCAP * nm / (double)NV);

    double s0 = 1.0, sA = 1.0, sB = 1.0;
    double z0 = 1.0, zA = 1.0, zB = 1.0;

    for (int it = 0; it < ITERS; ++it) {
        const uint32_t ph = (uint32_t)(it & 1);
        if (i == 0) {
            mb_expect(barA, CL*5*8);
            mb_expect(barB, CL*2*8);
            mb_expect(barC, CL*2*8);
            mb_expect(barD, CL*2*8);
            mb_expect(barE, CL*3*8);
        }

        // scalar reciprocals (prev-state only)
        const double inv_sss = 1.0 / (s0 * sA * sB);
        const double is0 = sA * sB * inv_sss;
        const double isA = s0 * sB * inv_sss;
        const double isB = s0 * sA * inv_sss;
        const double w0 = z0 * is0, wA = zA * isA, wB = zB * isB;
        const double M11p = s0 / z0;
        const double M22p = 1.0 / (wA + wB);

        // ================= Round A: diag + residual sums =================
        const double ss    = s1 * s2;
        const double invss = 1.0 / ss;
        const double invs1 = s2 * invss;
        const double invs2 = s1 * invss;
        const double den   = fma((double)EPSR, ss, fma(z1, s2, z2 * s1));
        const double invD  = ss / den;
        {
            double v0 = wsum(xi);
            double v1 = wsum(fi * xi);
            double v2 = wsum(s1 * z1 + s2 * z2);
            double v3 = wsum(invD);
            double v4 = wsum(fi * invD);
            if (lane == 0) {
                lpart[wid][0]=v0; lpart[wid][1]=v1; lpart[wid][2]=v2;
                lpart[wid][3]=v3; lpart[wid][4]=v4;
            }
        }
        __syncthreads();
        if (wid == 0 && lane < CL) {
            uint32_t rb = mapa_u32(barA, lane);
            uint32_t ra = mapa_u32(s2u(&mA[rank][0]), lane);
            st_async_d(ra,      TREE4(lpart, 0), rb);
            st_async_d(ra + 8,  TREE4(lpart, 1), rb);
            st_async_d(ra + 16, TREE4(lpart, 2), rb);
            st_async_d(ra + 24, TREE4(lpart, 3), rb);
            st_async_d(ra + 32, TREE4(lpart, 4), rb);
        }
        mb_wait(barA, ph);
        const double sumx = TREE8(mA, 0);
        const double fx   = TREE8(mA, 1);
        const double szv  = TREE8(mA, 2);
        const double SiD  = TREE8(mA, 3);
        const double SfD  = TREE8(mA, 4);

        const double rp0 = sumx + s0 - CCAP;
        const double rpA =  fx + sA - hA;
        const double rpB = -fx + sB - hB;
        const double SZTOT = szv + s0*z0 + sA*zA + sB*zB;
        const double mu  = SZTOT * IMCON;
        const double imu = 1.0 / mu;
        double T0 = w0*rp0 - z0;
        double TA = wA*rpA - zA;
        double TB = wB*rpB - zB;
        const double M11 = M11p + SiD;
        const double M22 = M22p + SfD;
        const double M12 = SfD;
        const double detinv = 1.0 / (M11*M22 - M12*M12);

        // ================= Round B: predictor rhs + Woodbury sums ========
        const double rp1 = s1 - xi;
        const double rp2 = xi + s2 - 1.0;
        const double w1  = z1 * invs1;
        const double w2  = z2 * invs2;
        const double rx  = EPSR*xi + pi + (z0 - z1 + z2 + fi*(zA - zB));
        double g;
        {
            double rhs = -(rx + T0 - (w1*rp1 - z1) + (w2*rp2 - z2) + fi*(TA - TB));
            g = rhs * invD;
            double v0 = wsum(g);
            double v1 = wsum(fi * g);
            if (lane == 0) { lpart[wid][0] = v0; lpart[wid][1] = v1; }
        }
        __syncthreads();
        if (wid == 0 && lane < CL) {
            uint32_t rb = mapa_u32(barB, lane);
            uint32_t ra = mapa_u32(s2u(&mB[rank][0]), lane);
            st_async_d(ra,     TREE4(lpart, 0), rb);
            st_async_d(ra + 8, TREE4(lpart, 1), rb);
        }
        mb_wait(barB, ph);
        const double u1 = TREE8(mB, 0);
        const double uf = TREE8(mB, 1);

        const double Y1 = (M22*u1 - M12*uf) * detinv;
        const double Y2 = (M11*uf - M12*u1) * detinv;
        const double sdx = u1 - Y1*SiD - Y2*SfD;
        const double fdx = uf - (Y1 + Y2)*SfD;
        const double ds0 = -rp0 - sdx;
        const double dsA = -rpA - fdx;
        const double dsB = -rpB + fdx;
        const double dz0 = -z0 - w0*ds0;
        const double dzA = -zA - wA*dsA;
        const double dzB = -zB - wB*dsB;
        double sc_q = fmax(fmax(-ds0,0.0)*is0, fmax(fmax(-dsA,0.0)*isA, fmax(-dsB,0.0)*isB));
        sc_q = fmax(sc_q, fmax(1.0 + ds0*is0, 0.0));
        sc_q = fmax(sc_q, fmax(1.0 + dsA*isA, 0.0));
        sc_q = fmax(sc_q, fmax(1.0 + dsB*isB, 0.0));

        // ========= Round C: affine dir, step max, Sum(ds dz) =============
        double prod1, prod2;
        {
            double dx  = g - (Y1 + fi*Y2) * invD;
            double ds1 = dx - rp1,  ds2 = -rp2 - dx;
            double dz1 = -z1 - w1*ds1;
            double dz2 = -z2 - w2*ds2;
            double r1 = ds1 * invs1, r2 = ds2 * invs2;
            double mq = fmax(sc_q, fmax(fmax(-r1, 0.0), fmax(-r2, 0.0)));
            mq = fmax(mq, fmax(fmax(1.0 + r1, 0.0), fmax(1.0 + r2, 0.0)));
            prod1 = ds1 * dz1;
            prod2 = ds2 * dz2;
            double v0 = wsum(prod1 + prod2);
            double v1 = wmaxr(mq);
            if (lane == 0) { lpart[wid][0] = v0; lpart[wid][1] = v1; }
        }
        __syncthreads();
        if (wid == 0 && lane < CL) {
            uint32_t rb = mapa_u32(barC, lane);
            uint32_t ra = mapa_u32(s2u(&mCx[rank][0]), lane);
            st_async_d(ra,     TREE4(lpart, 0), rb);
            double mq = fmax(fmax(lpart[0][1], lpart[1][1]), fmax(lpart[2][1], lpart[3][1]));
            st_async_d(ra + 8, mq, rb);
        }
        mb_wait(barC, ph);
        const double S2v  = TREE8(mCx, 0);
        const double qmax = TREE8MAX(mCx, 1);

        const double aaff = (qmax > 0.0) ? fmin(1.0, 1.0 / qmax) : 1.0;
        const double S2t  = S2v + ds0*dz0 + dsA*dzA + dsB*dzB;
        const double muaff = fma(aaff*aaff, S2t, SZTOT*(1.0 - aaff)) * IMCON;
        const double smu = muaff * muaff * muaff * (imu * imu);
        const double rsz0 = s0*z0 + ds0*dz0 - smu;
        const double rszA = sA*zA + dsA*dzA - smu;
        const double rszB = sB*zB + dsB*dzB - smu;
        T0 = (z0*rp0 - rsz0) * is0;
        TA = (zA*rpA - rszA) * isA;
        TB = (zB*rpB - rszB) * isB;

        // ========= Round D: corrector rhs + Woodbury sums ================
        const double rsz1 = s1*z1 + prod1 - smu;
        const double rsz2 = s2*z2 + prod2 - smu;
        {
            double t1 = (z1*rp1 - rsz1) * invs1;
            double t2 = (z2*rp2 - rsz2) * invs2;
            double rhs = -(rx + T0 - t1 + t2 + fi*(TA - TB));
            g = rhs * invD;
            double v0 = wsum(g);
            double v1 = wsum(fi * g);
            if (lane == 0) { lpart[wid][0] = v0; lpart[wid][1] = v1; }
        }
        __syncthreads();
        if (wid == 0 && lane < CL) {
            uint32_t rb = mapa_u32(barD, lane);
            uint32_t ra = mapa_u32(s2u(&mD[rank][0]), lane);
            st_async_d(ra,     TREE4(lpart, 0), rb);
            st_async_d(ra + 8, TREE4(lpart, 1), rb);
        }
        mb_wait(barD, ph);
        const double u1c = TREE8(mD, 0);
        const double ufc = TREE8(mD, 1);

        const double Y1c = (M22*u1c - M12*ufc) * detinv;
        const double Y2c = (M11*ufc - M12*u1c) * detinv;
        const double sdxc = u1c - Y1c*SiD - Y2c*SfD;
        const double fdxc = ufc - (Y1c + Y2c)*SfD;
        const double ds0c = -rp0 - sdxc;
        const double dsAc = -rpA - fdxc;
        const double dsBc = -rpB + fdxc;
        const double dz0c = -(rsz0 + z0*ds0c) * is0;
        const double dzAc = -(rszA + zA*dsAc) * isA;
        const double dzBc = -(rszB + zB*dsBc) * isB;
        double sc_qs = fmax(fmax(-ds0c,0.0)*is0,
                       fmax(fmax(-dsAc,0.0)*isA, fmax(-dsBc,0.0)*isB));
        double scn = fmax(-dz0c, 0.0), scd = z0;
        { double n2 = fmax(-dzAc,0.0), d2 = zA; if (n2*scd > scn*d2) { scn=n2; scd=d2; } }
        { double n2 = fmax(-dzBc,0.0), d2 = zB; if (n2*scd > scn*d2) { scn=n2; scd=d2; } }

        // ========= Round E: corrector dir + step + update ================
        double dxc, ds1c, ds2c, dz1c, dz2c;
        {
            dxc  = g - (Y1c + fi*Y2c) * invD;
            ds1c = dxc - rp1;
            ds2c = -rp2 - dxc;
            dz1c = -(rsz1 + z1*ds1c) * invs1;
            dz2c = -(rsz2 + z2*ds2c) * invs2;
            double mqs = fmax(sc_qs, fmax(fmax(-ds1c,0.0)*invs1, fmax(-ds2c,0.0)*invs2));
            double n1 = fmax(-dz1c, 0.0), d1v = z1;
            double n2 = fmax(-dz2c, 0.0), d2v = z2;
            if (n2*d1v > n1*d2v) { n1 = n2; d1v = d2v; }
            double pn = scn, pd = scd;
            if (n1*pd > pn*d1v)  { pn = n1; pd = d1v; }
            mqs = wmaxr(mqs);
            wpairmax(pn, pd);
            if (lane == 0) { lpart[wid][0] = mqs; lpart[wid][1] = pn; lpart[wid][2] = pd; }
        }
        __syncthreads();
        if (wid == 0 && lane < CL) {
            double mq = fmax(fmax(lpart[0][0], lpart[1][0]), fmax(lpart[2][0], lpart[3][0]));
            double n1 = lpart[0][1], d1v = lpart[0][2];
            double n2 = lpart[1][1], d2v = lpart[1][2];
            if (n2*d1v > n1*d2v) { n1 = n2; d1v = d2v; }
            double n3 = lpart[2][1], d3v = lpart[2][2];
            double n4 = lpart[3][1], d4v = lpart[3][2];
            if (n4*d3v > n3*d4v) { n3 = n4; d3v = d4v; }
            if (n3*d1v > n1*d3v) { n1 = n3; d1v = d3v; }
            uint32_t rb = mapa_u32(barE, lane);
            uint32_t ra = mapa_u32(s2u(&mE[rank][0]), lane);
            st_async_d(ra,      mq,  rb);
            st_async_d(ra + 8,  n1,  rb);
            st_async_d(ra + 16, d1v, rb);
        }
        mb_wait(barE, ph);
        const double mqs = TREE8MAX(mE, 0);
        double pn, pd;
        {
            double n1 = mE[0][1], d1v = mE[0][2];
            { double n2 = mE[1][1], d2v = mE[1][2]; if (n2*d1v > n1*d2v) { n1=n2; d1v=d2v; } }
            double n3 = mE[2][1], d3v = mE[2][2];
            { double n4 = mE[3][1], d4v = mE[3][2]; if (n4*d3v > n3*d4v) { n3=n4; d3v=d4v; } }
            if (n3*d1v > n1*d3v) { n1 = n3; d1v = d3v; }
            double n5 = mE[4][1], d5v = mE[4][2];
            { double n6 = mE[5][1], d6v = mE[5][2]; if (n6*d5v > n5*d6v) { n5=n6; d5v=d6v; } }
            double n7 = mE[6][1], d7v = mE[6][2];
            { double n8 = mE[7][1], d8v = mE[7][2]; if (n8*d7v > n7*d8v) { n7=n8; d7v=d8v; } }
            if (n7*d5v > n5*d7v) { n5 = n7; d5v = d7v; }
            if (n5*d1v > n1*d5v) { n1 = n5; d1v = d5v; }
            pn = n1; pd = d1v;
        }

        if (mqs * pd > pn) { pn = mqs; pd = 1.0; }
        const double st = (pn > 0.0) ? fmin(1.0, pd / pn) : 1.0;
        const double alpha = 0.99 * st;

        s0 += alpha*ds0c;  sA += alpha*dsAc;  sB += alpha*dsBc;
        z0 += alpha*dz0c;  zA += alpha*dzAc;  zB += alpha*dzBc;
        xi += alpha*dxc;
        s1 += alpha*ds1c;  z1 += alpha*dz1c;
        s2 += alpha*ds2c;  z2 += alpha*dz2c;
    }

    out[c] = (float)xi;
}

extern "C" void kernel_launch(void* const* d_in, const int* in_sizes, int n_in,
                              void* d_out, int out_size)
{
    const float* x    = (const float*)d_in[0];
    const int*   male = (const int*)d_in[1];
    float*       out  = (float*)d_out;
    pdip_kernel<<<CL, T>>>(x, male, out);
}